// round 2
// baseline (speedup 1.0000x reference)
#include <cuda_runtime.h>

// ---------------------------------------------------------------------------
// GraphSAGE 3-layer, fp32. N=50000 nodes, E=600000 edges, 128->128->128->40.
//   deg (once) -> rdeg
//   per layer: [t|s] = h @ [w_neigh|w_self]  (one fused GEMM, f32x2 FFMA)
//              msg[dst] += t[src]            (red.global.add.v4.f32)
//              h' = act(s + msg*rdeg + b)    (elementwise)
// Layer 3 transforms to 40 dims BEFORE aggregating (3.2x less atomic traffic).
// ---------------------------------------------------------------------------

static __device__ float g_TS [50000 * 256]; // fused GEMM output [t|s]
static __device__ float g_msg[50000 * 128]; // aggregation buffer
static __device__ float g_H  [50000 * 128]; // hidden activations
static __device__ float g_deg[50000];       // degree, then 1/max(deg,1)

__device__ __forceinline__ unsigned long long pack2(float x) {
    unsigned long long r;
    asm("mov.b64 %0, {%1, %1};" : "=l"(r) : "f"(x));
    return r;
}
__device__ __forceinline__ void ffma2(unsigned long long& d,
                                      unsigned long long a,
                                      unsigned long long b) {
    asm("fma.rn.f32x2 %0, %1, %2, %0;" : "+l"(d) : "l"(a), "l"(b));
}
__device__ __forceinline__ void red4(float* p, float4 v) {
    asm volatile("red.global.add.v4.f32 [%0], {%1, %2, %3, %4};"
                 :: "l"(p), "f"(v.x), "f"(v.y), "f"(v.z), "f"(v.w)
                 : "memory");
}
union U2F2 { unsigned long long u; float2 f; };

// ---------------------------------------------------------------------------
// small helpers
// ---------------------------------------------------------------------------
__global__ void zero_f4(float4* p, int n4) {
    int i = blockIdx.x * blockDim.x + threadIdx.x;
    if (i < n4) p[i] = make_float4(0.f, 0.f, 0.f, 0.f);
}

__global__ void deg_count(const int* __restrict__ dst, int E) {
    int i = blockIdx.x * blockDim.x + threadIdx.x;
    if (i < E) atomicAdd(&g_deg[dst[i]], 1.0f);
}

__global__ void rdeg_inv(int M) {
    int i = blockIdx.x * blockDim.x + threadIdx.x;
    if (i < M) g_deg[i] = 1.0f / fmaxf(g_deg[i], 1.0f);
}

// ---------------------------------------------------------------------------
// Fused GEMM: out[M x 2*DOUT] = A[M x 128] @ [Wn | Ws]   (no bias here)
// Full K=128 staged in smem. Register tile TM x (TNP f32x2 pairs).
// ---------------------------------------------------------------------------
template <int DOUT, int CT, int RT, int TM, int TNP>
__global__ void __launch_bounds__(CT * RT, 1)
gemm_fused(const float* __restrict__ A,
           const float* __restrict__ Wn,
           const float* __restrict__ Ws,
           float* __restrict__ out, int M) {
    constexpr int NOUT = 2 * DOUT;
    constexpr int BM = RT * TM;
    constexpr int NT = CT * RT;
    constexpr int ASTR = 132;  // padded A stride (words), 16B-aligned

    extern __shared__ float sm[];
    float* Wsh = sm;                 // [128 * NOUT]
    float* Ash = sm + 128 * NOUT;    // [BM][ASTR] row-major (rows of A)

    const int tid = threadIdx.x;
    const int row0 = blockIdx.x * BM;

    // stage W = [Wn | Ws] : 128 x NOUT
    for (int i = tid; i < 128 * (DOUT / 4); i += NT) {
        int k = i / (DOUT / 4);
        int c = (i % (DOUT / 4)) * 4;
        float4 wn = *reinterpret_cast<const float4*>(Wn + k * DOUT + c);
        float4 ws = *reinterpret_cast<const float4*>(Ws + k * DOUT + c);
        *reinterpret_cast<float4*>(Wsh + k * NOUT + c) = wn;
        *reinterpret_cast<float4*>(Wsh + k * NOUT + DOUT + c) = ws;
    }
    // stage A tile: BM x 128, row-major
    for (int i = tid; i < BM * 32; i += NT) {
        int r = i / 32;
        int kc = (i % 32) * 4;
        int gr = row0 + r;
        if (gr >= M) gr = M - 1;  // clamp read; stores guarded below
        float4 a = *reinterpret_cast<const float4*>(A + (size_t)gr * 128 + kc);
        *reinterpret_cast<float4*>(Ash + r * ASTR + kc) = a;
    }
    __syncthreads();

    const int ct = tid % CT;
    const int rt = tid / CT;
    const int colbase = ct * (TNP * 2);
    const float* arow = Ash + rt * TM * ASTR;

    unsigned long long acc[TM][TNP];
#pragma unroll
    for (int i = 0; i < TM; i++)
#pragma unroll
        for (int p = 0; p < TNP; p++) acc[i][p] = 0ull;

#pragma unroll 4
    for (int k = 0; k < 128; ++k) {
        unsigned long long w[TNP];
#pragma unroll
        for (int p = 0; p < TNP; p++)
            w[p] = *reinterpret_cast<const unsigned long long*>(
                Wsh + k * NOUT + colbase + 2 * p);
#pragma unroll
        for (int i = 0; i < TM; i++) {
            unsigned long long aa = pack2(arow[i * ASTR + k]);
#pragma unroll
            for (int p = 0; p < TNP; p++) ffma2(acc[i][p], aa, w[p]);
        }
    }

#pragma unroll
    for (int i = 0; i < TM; i++) {
        int gr = row0 + rt * TM + i;
        if (gr < M) {
            float* o = out + (size_t)gr * NOUT + colbase;
#pragma unroll
            for (int p = 0; p < TNP; p += 2) {
                U2F2 u0, u1;
                u0.u = acc[i][p];
                u1.u = acc[i][p + 1];
                float4 v = make_float4(u0.f.x, u0.f.y, u1.f.x, u1.f.y);
                *reinterpret_cast<float4*>(o + 2 * p) = v;
            }
        }
    }
}

// ---------------------------------------------------------------------------
// Aggregation: msg[dst] += t[src]. 128-wide: one warp per edge, float4/lane.
// ---------------------------------------------------------------------------
__global__ void agg128(const int* __restrict__ src, const int* __restrict__ dst,
                       int E) {
    int gt = blockIdx.x * blockDim.x + threadIdx.x;
    int e = gt >> 5;
    int lane = gt & 31;
    if (e >= E) return;
    int s = src[e];
    int d = dst[e];
    float4 v = *reinterpret_cast<const float4*>(g_TS + (size_t)s * 256 + lane * 4);
    red4(g_msg + (size_t)d * 128 + lane * 4, v);
}

// 40-wide (layer 3): 10 float4 chunks per edge, flat indexing.
__global__ void agg40(const int* __restrict__ src, const int* __restrict__ dst,
                      int E) {
    int i = blockIdx.x * blockDim.x + threadIdx.x;
    if (i >= E * 10) return;
    int e = i / 10;
    int c = i - e * 10;
    int s = src[e];
    int d = dst[e];
    float4 v = *reinterpret_cast<const float4*>(g_TS + (size_t)s * 80 + c * 4);
    red4(g_msg + (size_t)d * 40 + c * 4, v);
}

// ---------------------------------------------------------------------------
// Combine: out = act(s + msg * rdeg + b).  s lives in TS[:, DOUT:2*DOUT].
// ---------------------------------------------------------------------------
template <int DOUT, bool RELU>
__global__ void comb(const float* __restrict__ TS, const float* __restrict__ b,
                     float* __restrict__ out, int M) {
    int i = blockIdx.x * blockDim.x + threadIdx.x;
    constexpr int C4 = DOUT / 4;
    if (i >= M * C4) return;
    int row = i / C4;
    int c = (i - row * C4) * 4;
    float4 s = *reinterpret_cast<const float4*>(TS + (size_t)row * (2 * DOUT) + DOUT + c);
    float4 m = *reinterpret_cast<const float4*>(g_msg + (size_t)row * DOUT + c);
    float4 bb = *reinterpret_cast<const float4*>(b + c);
    float r = g_deg[row];
    float4 v;
    v.x = s.x + m.x * r + bb.x;
    v.y = s.y + m.y * r + bb.y;
    v.z = s.z + m.z * r + bb.z;
    v.w = s.w + m.w * r + bb.w;
    if (RELU) {
        v.x = fmaxf(v.x, 0.f); v.y = fmaxf(v.y, 0.f);
        v.z = fmaxf(v.z, 0.f); v.w = fmaxf(v.w, 0.f);
    }
    *reinterpret_cast<float4*>(out + (size_t)row * DOUT + c) = v;
}

// ---------------------------------------------------------------------------
// launch
// ---------------------------------------------------------------------------
static inline int cdiv(int a, int b) { return (a + b - 1) / b; }

extern "C" void kernel_launch(void* const* d_in, const int* in_sizes, int n_in,
                              void* d_out, int out_size) {
    const float* feat = (const float*)d_in[0];
    const int*   src  = (const int*)d_in[1];
    const int*   dst  = (const int*)d_in[2];
    const float* wS0 = (const float*)d_in[3];
    const float* wN0 = (const float*)d_in[4];
    const float* b0  = (const float*)d_in[5];
    const float* wS1 = (const float*)d_in[6];
    const float* wN1 = (const float*)d_in[7];
    const float* b1  = (const float*)d_in[8];
    const float* wS2 = (const float*)d_in[9];
    const float* wN2 = (const float*)d_in[10];
    const float* b2  = (const float*)d_in[11];
    float* out = (float*)d_out;

    const int M = in_sizes[0] / 128;
    const int E = in_sizes[1];

    void *pTS, *pMsg, *pH, *pDeg;
    cudaGetSymbolAddress(&pTS, g_TS);
    cudaGetSymbolAddress(&pMsg, g_msg);
    cudaGetSymbolAddress(&pH, g_H);
    cudaGetSymbolAddress(&pDeg, g_deg);
    float* TS = (float*)pTS;
    float* H = (float*)pH;
    float4* msg4 = (float4*)pMsg;
    float4* deg4 = (float4*)pDeg;

    // GEMM smem opt-in (idempotent; do once per process)
    constexpr int SMEM_A = (128 * 256 + 128 * 132) * 4;  // 198656 B
    constexpr int SMEM_B = (128 * 80 + 128 * 132) * 4;   // 108544 B
    static bool attr_done = false;
    if (!attr_done) {
        cudaFuncSetAttribute((const void*)gemm_fused<128, 32, 16, 8, 4>,
                             cudaFuncAttributeMaxDynamicSharedMemorySize, SMEM_A);
        cudaFuncSetAttribute((const void*)gemm_fused<40, 10, 32, 4, 4>,
                             cudaFuncAttributeMaxDynamicSharedMemorySize, SMEM_B);
        attr_done = true;
    }

    const int gemm_blocks = cdiv(M, 128);
    const int msg128_n4 = M * 128 / 4;
    const int msg40_n4 = M * 40 / 4;

    // degree (once)
    zero_f4<<<cdiv(M, 4 * 256), 256>>>(deg4, M / 4);
    deg_count<<<cdiv(E, 256), 256>>>(dst, E);
    rdeg_inv<<<cdiv(M, 256), 256>>>(M);

    // ---- layer 1 ----
    gemm_fused<128, 32, 16, 8, 4><<<gemm_blocks, 512, SMEM_A>>>(feat, wN0, wS0, TS, M);
    zero_f4<<<cdiv(msg128_n4, 256), 256>>>(msg4, msg128_n4);
    agg128<<<cdiv(E * 32, 256), 256>>>(src, dst, E);
    comb<128, true><<<cdiv(M * 32, 256), 256>>>(TS, b0, H, M);

    // ---- layer 2 ----
    gemm_fused<128, 32, 16, 8, 4><<<gemm_blocks, 512, SMEM_A>>>(H, wN1, wS1, TS, M);
    zero_f4<<<cdiv(msg128_n4, 256), 256>>>(msg4, msg128_n4);
    agg128<<<cdiv(E * 32, 256), 256>>>(src, dst, E);
    comb<128, true><<<cdiv(M * 32, 256), 256>>>(TS, b1, H, M);

    // ---- layer 3 (40-wide, no relu) ----
    gemm_fused<40, 10, 32, 4, 4><<<gemm_blocks, 320, SMEM_B>>>(H, wN2, wS2, TS, M);
    zero_f4<<<cdiv(msg40_n4, 256), 256>>>(msg4, msg40_n4);
    agg40<<<cdiv(E * 10, 256), 256>>>(src, dst, E);
    comb<40, false><<<cdiv(M * 10, 256), 256>>>(TS, b2, out, M);
}